// round 4
// baseline (speedup 1.0000x reference)
#include <cuda_runtime.h>
#include <cuda_bf16.h>
#include <math.h>
#include <stdint.h>

#define N_VEC   16384
#define K_CODES 8192
#define DDIM    64
#define OUT_ELEMS 1048576            // 16*64*32*32
#define NTILES  64                   // 8192 / 128
#define MARGIN  1.5e-3f

// ---------------------------------------------------------------------------
// scratch (no cudaMalloc allowed)
__device__ __align__(256) float          g_cn[K_CODES * DDIM];   // normalized codebook fp32
__device__ __align__(256) __nv_bfloat16  g_cbH[K_CODES * DDIM];  // normalized codebook bf16 hi
__device__ __align__(256) __nv_bfloat16  g_cbL[K_CODES * DDIM];  // lo
__device__ __align__(256) __nv_bfloat16  g_zH[N_VEC * DDIM];     // z transposed [n][k] bf16 hi
__device__ __align__(256) __nv_bfloat16  g_zL[N_VEC * DDIM];     // lo
__device__ int    g_idx[N_VEC];
__device__ int    g_bin[K_CODES];
__device__ int    g_flag[N_VEC];
__device__ int    g_nflag;
__device__ double g_lossd;

// ---------------------------------------------------------------------------
__device__ __forceinline__ uint32_t smem_u32(const void* p) {
    uint32_t a;
    asm("{ .reg .u64 t; cvta.to.shared.u64 t, %1; cvt.u32.u64 %0, t; }"
        : "=r"(a) : "l"(p));
    return a;
}
__device__ __forceinline__ void cpa16(uint32_t s, const void* g) {
    asm volatile("cp.async.cg.shared.global [%0], [%1], 16;" :: "r"(s), "l"(g));
}
#define CP_COMMIT() asm volatile("cp.async.commit_group;" ::: "memory")
#define CP_WAIT0()  asm volatile("cp.async.wait_group 0;" ::: "memory")
#define CP_WAIT2()  asm volatile("cp.async.wait_group 2;" ::: "memory")

__device__ __forceinline__ void ldsm4(uint32_t* r, uint32_t addr) {
    asm volatile("ldmatrix.sync.aligned.m8n8.x4.shared.b16 {%0,%1,%2,%3}, [%4];"
                 : "=r"(r[0]), "=r"(r[1]), "=r"(r[2]), "=r"(r[3]) : "r"(addr));
}
__device__ __forceinline__ void mma_bf16(float* c, const uint32_t* a,
                                         uint32_t b0, uint32_t b1) {
    asm volatile("mma.sync.aligned.m16n8k16.row.col.f32.bf16.bf16.f32 "
                 "{%0,%1,%2,%3}, {%4,%5,%6,%7}, {%8,%9}, {%0,%1,%2,%3};"
                 : "+f"(c[0]), "+f"(c[1]), "+f"(c[2]), "+f"(c[3])
                 : "r"(a[0]), "r"(a[1]), "r"(a[2]), "r"(a[3]), "r"(b0), "r"(b1));
}
#define SW(x) ((x) ^ (((x) >> 3) & 0x70))

// ---------------------------------------------------------------------------
__global__ void zero_kernel() {
    int t = blockIdx.x * blockDim.x + threadIdx.x;
    if (t < K_CODES) g_bin[t] = 0;
    if (t == 0) { g_lossd = 0.0; g_nflag = 0; }
}

// ---------------------------------------------------------------------------
// Normalize codebook -> fp32 + bf16 hi/lo. warp per row.
__global__ void norm_split_kernel(const float* __restrict__ embed) {
    int wid = threadIdx.x >> 5, lane = threadIdx.x & 31;
    int row = blockIdx.x * 8 + wid;
    float a = embed[row * 64 + lane];
    float b = embed[row * 64 + lane + 32];
    float s = a * a + b * b;
#pragma unroll
    for (int off = 16; off >= 1; off >>= 1) s += __shfl_xor_sync(0xFFFFFFFFu, s, off);
    float inv = 1.0f / fmaxf(sqrtf(s), 1e-12f);
    float ca = a * inv, cb = b * inv;
    g_cn[row * 64 + lane] = ca;
    g_cn[row * 64 + lane + 32] = cb;
    __nv_bfloat16 ha = __float2bfloat16(ca), hb = __float2bfloat16(cb);
    g_cbH[row * 64 + lane] = ha;
    g_cbH[row * 64 + lane + 32] = hb;
    g_cbL[row * 64 + lane] = __float2bfloat16(ca - __bfloat162float(ha));
    g_cbL[row * 64 + lane + 32] = __float2bfloat16(cb - __bfloat162float(hb));
}

// ---------------------------------------------------------------------------
// Transpose z -> [n][k] bf16 hi/lo.
__global__ void z_split_kernel(const float* __restrict__ z) {
    __shared__ float tile[64 * 128];
    int b = blockIdx.x >> 3;
    int hwb = blockIdx.x & 7;
    int t = threadIdx.x;
    const float4* z4 = (const float4*)z;
#pragma unroll
    for (int i = 0; i < 8; i++) {
        int f4 = t + i * 256;
        int k = f4 >> 5, w = f4 & 31;
        *(float4*)&tile[k * 128 + w * 4] = z4[b * 16384 + k * 256 + hwb * 32 + w];
    }
    __syncthreads();
    int r = t >> 1, half = t & 1;
    int n = b * 1024 + hwb * 128 + r;
#pragma unroll
    for (int kk = 0; kk < 32; kk++) {
        int k = half * 32 + kk;
        float v = tile[k * 128 + r];
        __nv_bfloat16 h = __float2bfloat16(v);
        g_zH[n * 64 + k] = h;
        g_zL[n * 64 + k] = __float2bfloat16(v - __bfloat162float(h));
    }
}

// ---------------------------------------------------------------------------
// Main kernel: mma.sync bf16x3 GEMM + fused running argmax (top-2).
// 256 threads, warp grid 4(M) x 2(N). A fragments in registers.
// Dyn smem: 4 stages x 32KB (Bh 16K | Bl 16K), 1024-aligned.
extern __shared__ char dsm[];
__global__ void __launch_bounds__(256, 1) hmma_argmax_kernel() {
    uint32_t sraw = smem_u32(dsm);
    uint32_t dbase = (sraw + 1023) & ~1023u;
    char* dp = dsm + (int)(dbase - sraw);
    int tid = threadIdx.x, lane = tid & 31, wid = tid >> 5;
    int wm = wid & 3, wn = wid >> 2;
    int nbase = blockIdx.x * 128;

    // ---- A prologue: stage zH/zL rows into stage0, swizzled ----
    {
        const int4* h4 = (const int4*)g_zH;
        const int4* l4 = (const int4*)g_zL;
#pragma unroll
        for (int w = 0; w < 4; w++) {
            int i = tid + w * 256;
            int r = i >> 3, c = i & 7;
            cpa16(dbase + SW(r * 128 + c * 16), &h4[(nbase + r) * 8 + c]);
            cpa16(dbase + 16384 + SW(r * 128 + c * 16), &l4[(nbase + r) * 8 + c]);
        }
        CP_COMMIT();
        CP_WAIT0();
        __syncthreads();
    }

    // ---- load A fragments (held in registers for whole kernel) ----
    uint32_t ah[2][4][4], al[2][4][4];
    {
        int rA = ((lane >> 3) & 1) * 8 + (lane & 7);
        int kA = (lane >> 4) * 16;
#pragma unroll
        for (int mf = 0; mf < 2; mf++)
#pragma unroll
            for (int ks = 0; ks < 4; ks++) {
                uint32_t off = SW((uint32_t)((wm * 32 + mf * 16 + rA) * 128 + ks * 32 + kA));
                ldsm4(ah[mf][ks], dbase + off);
                ldsm4(al[mf][ks], dbase + 16384 + off);
            }
    }
    __syncthreads();   // done reading stage0 before B pipeline reuses it

    // ---- precompute swizzled B ldmatrix offsets (lane-dependent, stage-invariant) ----
    uint32_t offB[4][4];
    {
        int rB = ((lane >> 4) & 1) * 8 + (lane & 7);
        int kB = ((lane >> 3) & 1) * 16;
#pragma unroll
        for (int ks = 0; ks < 4; ks++)
#pragma unroll
            for (int p = 0; p < 4; p++)
                offB[ks][p] = SW((uint32_t)((wn * 64 + p * 16 + rB) * 128 + ks * 32 + kB));
    }

    // ---- prefetch offsets ----
    uint32_t pf_s[4];
    int pf_g[4];
#pragma unroll
    for (int w = 0; w < 4; w++) {
        int i = tid + w * 256;
        int r = i >> 3, c = i & 7;
        pf_s[w] = SW((uint32_t)(r * 128 + c * 16));
        pf_g[w] = r * 8 + c;
    }
    const int4* cbh4 = (const int4*)g_cbH;
    const int4* cbl4 = (const int4*)g_cbL;

    auto prefetch = [&](int nt) {
        uint32_t st = dbase + (nt & 3) * 32768;
#pragma unroll
        for (int w = 0; w < 4; w++) {
            cpa16(st + pf_s[w], &cbh4[nt * 1024 + pf_g[w]]);
            cpa16(st + 16384 + pf_s[w], &cbl4[nt * 1024 + pf_g[w]]);
        }
        CP_COMMIT();
    };

    prefetch(0); prefetch(1); prefetch(2);

    float g1[4], g2[4];
    int gi[4];
#pragma unroll
    for (int s = 0; s < 4; s++) { g1[s] = -1e30f; g2[s] = -1e30f; gi[s] = 0; }

    for (int nt = 0; nt < NTILES; nt++) {
        CP_WAIT2();
        __syncthreads();
        if (nt < NTILES - 3) prefetch(nt + 3);
        uint32_t stage = dbase + (nt & 3) * 32768;

        float C[2][8][4];
#pragma unroll
        for (int mf = 0; mf < 2; mf++)
#pragma unroll
            for (int j = 0; j < 8; j++)
#pragma unroll
                for (int q = 0; q < 4; q++) C[mf][j][q] = 0.0f;

#pragma unroll
        for (int ks = 0; ks < 4; ks++) {
            uint32_t bh[4][4];
#pragma unroll
            for (int p = 0; p < 4; p++) ldsm4(bh[p], stage + offB[ks][p]);
#pragma unroll
            for (int mf = 0; mf < 2; mf++)
#pragma unroll
                for (int p = 0; p < 4; p++) {
                    mma_bf16(C[mf][2 * p],     ah[mf][ks], bh[p][0], bh[p][1]);
                    mma_bf16(C[mf][2 * p + 1], ah[mf][ks], bh[p][2], bh[p][3]);
                }
#pragma unroll
            for (int mf = 0; mf < 2; mf++)
#pragma unroll
                for (int p = 0; p < 4; p++) {
                    mma_bf16(C[mf][2 * p],     al[mf][ks], bh[p][0], bh[p][1]);
                    mma_bf16(C[mf][2 * p + 1], al[mf][ks], bh[p][2], bh[p][3]);
                }
            uint32_t bl[4][4];
#pragma unroll
            for (int p = 0; p < 4; p++) ldsm4(bl[p], stage + 16384 + offB[ks][p]);
#pragma unroll
            for (int mf = 0; mf < 2; mf++)
#pragma unroll
                for (int p = 0; p < 4; p++) {
                    mma_bf16(C[mf][2 * p],     ah[mf][ks], bl[p][0], bl[p][1]);
                    mma_bf16(C[mf][2 * p + 1], ah[mf][ks], bl[p][2], bl[p][3]);
                }
        }

        // ---- running top-2 argmax update ----
        int cb = nt * 128 + wn * 64 + (lane & 3) * 2;
#pragma unroll
        for (int mf = 0; mf < 2; mf++)
#pragma unroll
            for (int h = 0; h < 2; h++) {
                int s = mf * 2 + h;
                float m[8];
#pragma unroll
                for (int j = 0; j < 8; j++)
                    m[j] = fmaxf(C[mf][j][2 * h], C[mf][j][2 * h + 1]);
                m[0] = fmaxf(m[0], m[1]); m[2] = fmaxf(m[2], m[3]);
                m[4] = fmaxf(m[4], m[5]); m[6] = fmaxf(m[6], m[7]);
                m[0] = fmaxf(m[0], m[2]); m[4] = fmaxf(m[4], m[6]);
                float tm = fmaxf(m[0], m[4]);
                if (tm > g1[s]) {
                    float m1 = -1e30f, m2 = -1e30f;
                    int mi = 0;
#pragma unroll
                    for (int j = 0; j < 8; j++)
#pragma unroll
                        for (int c = 0; c < 2; c++) {
                            float v = C[mf][j][2 * h + c];
                            int col = cb + j * 8 + c;
                            if (v > m1) { m2 = m1; m1 = v; mi = col; }
                            else if (v > m2) { m2 = v; }
                        }
                    g2[s] = fmaxf(g1[s], m2);
                    g1[s] = m1;
                    gi[s] = mi;
                } else {
                    g2[s] = fmaxf(g2[s], tm);
                }
            }
    }
    __syncthreads();

    // ---- quad reduce (lanes sharing rows: lane^1, lane^2) ----
#pragma unroll
    for (int s = 0; s < 4; s++) {
#pragma unroll
        for (int d = 1; d <= 2; d <<= 1) {
            float ov1 = __shfl_xor_sync(0xFFFFFFFFu, g1[s], d);
            float ov2 = __shfl_xor_sync(0xFFFFFFFFu, g2[s], d);
            int   oi  = __shfl_xor_sync(0xFFFFFFFFu, gi[s], d);
            if (ov1 > g1[s]) { g2[s] = fmaxf(g1[s], ov2); g1[s] = ov1; gi[s] = oi; }
            else {
                if (ov1 == g1[s] && oi < gi[s]) gi[s] = oi;
                g2[s] = fmaxf(g2[s], ov1);
            }
        }
    }

    // ---- cross-warp (wn) reduce via smem ----
    float* rv1 = (float*)dp;          // [2][128]
    float* rv2 = rv1 + 256;           // [2][128]
    int*   ri  = (int*)(rv2 + 256);   // [2][128]
    if ((lane & 3) == 0) {
#pragma unroll
        for (int s = 0; s < 4; s++) {
            int mf = s >> 1, h = s & 1;
            int row = wm * 32 + mf * 16 + h * 8 + (lane >> 2);
            rv1[wn * 128 + row] = g1[s];
            rv2[wn * 128 + row] = g2[s];
            ri[wn * 128 + row]  = gi[s];
        }
    }
    __syncthreads();
    if (tid < 128) {
        float a1 = rv1[tid], a2 = rv2[tid];
        int   ai = ri[tid];
        float b1 = rv1[128 + tid], b2 = rv2[128 + tid];
        int   bi = ri[128 + tid];
        float v1, v2; int i1;
        if (b1 > a1)      { v1 = b1; v2 = fmaxf(a1, b2); i1 = bi; }
        else if (a1 > b1) { v1 = a1; v2 = fmaxf(a2, b1); i1 = ai; }
        else              { v1 = a1; v2 = a1; i1 = (ai < bi) ? ai : bi; }
        g_idx[nbase + tid] = i1;
        if (v1 - v2 < MARGIN) {
            int slot = atomicAdd(&g_nflag, 1);
            g_flag[slot] = nbase + tid;
        }
    }
}

// ---------------------------------------------------------------------------
// Exact fp32 rescore of flagged rows. warp per row.
__global__ void rescore_kernel(const float* __restrict__ z) {
    __shared__ float zrow[8][64];
    int wid = threadIdx.x >> 5, lane = threadIdx.x & 31;
    int gw = blockIdx.x * 8 + wid;
    int nf = g_nflag;
    for (int f = gw; f < nf; f += 64 * 8) {
        int n = g_flag[f];
        int b = n >> 10, hw = n & 1023;
        zrow[wid][lane]      = z[b * 65536 + lane * 1024 + hw];
        zrow[wid][lane + 32] = z[b * 65536 + (lane + 32) * 1024 + hw];
        __syncwarp();
        float v1 = -1e30f; int i1 = 0;
        for (int j = lane; j < K_CODES; j += 32) {
            const float4* cr = (const float4*)(g_cn + j * 64);
            float s = 0.0f;
#pragma unroll
            for (int q = 0; q < 16; q++) {
                float4 cv = cr[q];
                s += cv.x * zrow[wid][q * 4 + 0];
                s += cv.y * zrow[wid][q * 4 + 1];
                s += cv.z * zrow[wid][q * 4 + 2];
                s += cv.w * zrow[wid][q * 4 + 3];
            }
            if (s > v1) { v1 = s; i1 = j; }
        }
#pragma unroll
        for (int off = 16; off >= 1; off >>= 1) {
            float ov = __shfl_xor_sync(0xFFFFFFFFu, v1, off);
            int   oi = __shfl_xor_sync(0xFFFFFFFFu, i1, off);
            if (ov > v1 || (ov == v1 && oi < i1)) { v1 = ov; i1 = oi; }
        }
        if (lane == 0) g_idx[n] = i1;
        __syncwarp();
    }
}

// ---------------------------------------------------------------------------
__global__ void bincount_kernel() {
    int t = blockIdx.x * blockDim.x + threadIdx.x;
    if (t < N_VEC) atomicAdd(&g_bin[g_idx[t]], 1);
}

// ---------------------------------------------------------------------------
// Coalesced gather + loss.
__global__ void gather_kernel(const float* __restrict__ z,
                              const float* __restrict__ embed,
                              float* __restrict__ out) {
    __shared__ float qt[64 * 128];
    int t = threadIdx.x;
    int nbase = blockIdx.x * 128;
    int b = nbase >> 10, hw0 = nbase & 1023;

    {
        int r = t >> 1, half = t & 1;
        int idx = g_idx[nbase + r];
        const float4* er = (const float4*)(embed + idx * 64 + half * 32);
#pragma unroll
        for (int q = 0; q < 8; q++) {
            float4 v = er[q];
            int k = half * 32 + q * 4;
            qt[(k + 0) * 128 + r] = v.x;
            qt[(k + 1) * 128 + r] = v.y;
            qt[(k + 2) * 128 + r] = v.z;
            qt[(k + 3) * 128 + r] = v.w;
        }
    }
    __syncthreads();

    float s = 0.0f;
#pragma unroll
    for (int i = 0; i < 8; i++) {
        int f4 = t + i * 256;
        int k = f4 >> 5, hw4 = (f4 & 31) * 4;
        float4 qv = *(float4*)&qt[k * 128 + hw4];
        int off = b * 65536 + k * 1024 + hw0 + hw4;
        float4 zv = *(const float4*)&z[off];
        *(float4*)&out[off] = qv;
        float d0 = qv.x - zv.x, d1 = qv.y - zv.y, d2 = qv.z - zv.z, d3 = qv.w - zv.w;
        s += d0 * d0 + d1 * d1 + d2 * d2 + d3 * d3;
    }
#pragma unroll
    for (int off = 16; off >= 1; off >>= 1) s += __shfl_xor_sync(0xFFFFFFFFu, s, off);
    __shared__ float red[8];
    int lane = t & 31, wid = t >> 5;
    if (lane == 0) red[wid] = s;
    __syncthreads();
    if (wid == 0) {
        s = (lane < 8) ? red[lane] : 0.0f;
#pragma unroll
        for (int off = 4; off >= 1; off >>= 1) s += __shfl_xor_sync(0xFFFFFFFFu, s, off);
        if (lane == 0) atomicAdd(&g_lossd, (double)s);
    }
}

// ---------------------------------------------------------------------------
__global__ void finalize_kernel(float* __restrict__ out) {
    int t = blockIdx.x * blockDim.x + threadIdx.x;
    if (t == 0)
        out[OUT_ELEMS] = (float)(1.25 * g_lossd * (1.0 / (double)OUT_ELEMS));
    if (t < N_VEC)
        out[OUT_ELEMS + 1 + t] = (float)g_idx[t];
    if (t < K_CODES)
        out[OUT_ELEMS + 1 + N_VEC + t] = (float)g_bin[t];
}

// ---------------------------------------------------------------------------
extern "C" void kernel_launch(void* const* d_in, const int* in_sizes, int n_in,
                              void* d_out, int out_size) {
    const float* z     = (const float*)d_in[0];       // [16,64,32,32]
    const float* embed = (const float*)d_in[1];       // [8192,64]
    float* out = (float*)d_out;

    cudaFuncSetAttribute(hmma_argmax_kernel,
                         cudaFuncAttributeMaxDynamicSharedMemorySize, 132096);

    zero_kernel<<<64, 256>>>();
    norm_split_kernel<<<K_CODES / 8, 256>>>(embed);
    z_split_kernel<<<128, 256>>>(z);
    hmma_argmax_kernel<<<128, 256, 132096>>>();
    rescore_kernel<<<64, 256>>>(z);
    bincount_kernel<<<64, 256>>>();
    gather_kernel<<<128, 256>>>(z, embed, out);
    finalize_kernel<<<96, 256>>>(out);
}

// round 5
// speedup vs baseline: 1.2180x; 1.2180x over previous
#include <cuda_runtime.h>
#include <cuda_bf16.h>
#include <math.h>
#include <stdint.h>

#define N_VEC   16384
#define K_CODES 8192
#define DDIM    64
#define OUT_ELEMS 1048576            // 16*64*32*32
#define NTILES  64                   // 8192 / 128
#define MARGIN  1e-4f

// ---------------------------------------------------------------------------
// scratch (no cudaMalloc allowed)
__device__ __align__(256) float          g_cn[K_CODES * DDIM];   // normalized codebook fp32
__device__ __align__(256) __nv_bfloat16  g_cbH[K_CODES * DDIM];  // normalized codebook bf16 hi
__device__ __align__(256) __nv_bfloat16  g_cbL[K_CODES * DDIM];  // lo
__device__ __align__(256) __nv_bfloat16  g_zH[N_VEC * DDIM];     // z transposed [n][k] bf16 hi
__device__ __align__(256) __nv_bfloat16  g_zL[N_VEC * DDIM];     // lo
__device__ int    g_idx[N_VEC];
__device__ int    g_bin[K_CODES];
__device__ int    g_flag[N_VEC];
__device__ int    g_nflag;
__device__ double g_lossd;

// ---------------------------------------------------------------------------
__device__ __forceinline__ uint32_t smem_u32(const void* p) {
    uint32_t a;
    asm("{ .reg .u64 t; cvta.to.shared.u64 t, %1; cvt.u32.u64 %0, t; }"
        : "=r"(a) : "l"(p));
    return a;
}
__device__ __forceinline__ void cpa16(uint32_t s, const void* g) {
    asm volatile("cp.async.cg.shared.global [%0], [%1], 16;" :: "r"(s), "l"(g));
}
#define CP_COMMIT() asm volatile("cp.async.commit_group;" ::: "memory")
#define CP_WAIT0()  asm volatile("cp.async.wait_group 0;" ::: "memory")
#define CP_WAIT2()  asm volatile("cp.async.wait_group 2;" ::: "memory")

__device__ __forceinline__ void ldsm4(uint32_t* r, uint32_t addr) {
    asm volatile("ldmatrix.sync.aligned.m8n8.x4.shared.b16 {%0,%1,%2,%3}, [%4];"
                 : "=r"(r[0]), "=r"(r[1]), "=r"(r[2]), "=r"(r[3]) : "r"(addr));
}
__device__ __forceinline__ void mma_bf16(float* c, const uint32_t* a,
                                         uint32_t b0, uint32_t b1) {
    asm volatile("mma.sync.aligned.m16n8k16.row.col.f32.bf16.bf16.f32 "
                 "{%0,%1,%2,%3}, {%4,%5,%6,%7}, {%8,%9}, {%0,%1,%2,%3};"
                 : "+f"(c[0]), "+f"(c[1]), "+f"(c[2]), "+f"(c[3])
                 : "r"(a[0]), "r"(a[1]), "r"(a[2]), "r"(a[3]), "r"(b0), "r"(b1));
}
#define SW(x) ((x) ^ (((x) >> 3) & 0x70))

// ---------------------------------------------------------------------------
__global__ void zero_kernel() {
    int t = blockIdx.x * blockDim.x + threadIdx.x;
    if (t < K_CODES) g_bin[t] = 0;
    if (t == 0) { g_lossd = 0.0; g_nflag = 0; }
}

// ---------------------------------------------------------------------------
// Normalize codebook -> fp32 + bf16 hi/lo. warp per row.
__global__ void norm_split_kernel(const float* __restrict__ embed) {
    int wid = threadIdx.x >> 5, lane = threadIdx.x & 31;
    int row = blockIdx.x * 8 + wid;
    float a = embed[row * 64 + lane];
    float b = embed[row * 64 + lane + 32];
    float s = a * a + b * b;
#pragma unroll
    for (int off = 16; off >= 1; off >>= 1) s += __shfl_xor_sync(0xFFFFFFFFu, s, off);
    float inv = 1.0f / fmaxf(sqrtf(s), 1e-12f);
    float ca = a * inv, cb = b * inv;
    g_cn[row * 64 + lane] = ca;
    g_cn[row * 64 + lane + 32] = cb;
    __nv_bfloat16 ha = __float2bfloat16(ca), hb = __float2bfloat16(cb);
    g_cbH[row * 64 + lane] = ha;
    g_cbH[row * 64 + lane + 32] = hb;
    g_cbL[row * 64 + lane] = __float2bfloat16(ca - __bfloat162float(ha));
    g_cbL[row * 64 + lane + 32] = __float2bfloat16(cb - __bfloat162float(hb));
}

// ---------------------------------------------------------------------------
// Transpose z -> [n][k] bf16 hi/lo.
__global__ void z_split_kernel(const float* __restrict__ z) {
    __shared__ float tile[64 * 128];
    int b = blockIdx.x >> 3;
    int hwb = blockIdx.x & 7;
    int t = threadIdx.x;
    const float4* z4 = (const float4*)z;
#pragma unroll
    for (int i = 0; i < 8; i++) {
        int f4 = t + i * 256;
        int k = f4 >> 5, w = f4 & 31;
        *(float4*)&tile[k * 128 + w * 4] = z4[b * 16384 + k * 256 + hwb * 32 + w];
    }
    __syncthreads();
    int r = t >> 1, half = t & 1;
    int n = b * 1024 + hwb * 128 + r;
#pragma unroll
    for (int kk = 0; kk < 32; kk++) {
        int k = half * 32 + kk;
        float v = tile[k * 128 + r];
        __nv_bfloat16 h = __float2bfloat16(v);
        g_zH[n * 64 + k] = h;
        g_zL[n * 64 + k] = __float2bfloat16(v - __bfloat162float(h));
    }
}

// ---------------------------------------------------------------------------
// Main kernel: mma.sync bf16x3 GEMM + fused running argmax (top-2).
// 256 threads, warp grid 4(M) x 2(N). A fragments in registers.
// Dyn smem: 4 stages x 32KB (Bh 16K | Bl 16K), 1024-aligned.
extern __shared__ char dsm[];
__global__ void __launch_bounds__(256, 1) hmma_argmax_kernel() {
    uint32_t sraw = smem_u32(dsm);
    uint32_t dbase = (sraw + 1023) & ~1023u;
    char* dp = dsm + (int)(dbase - sraw);
    int tid = threadIdx.x, lane = tid & 31, wid = tid >> 5;
    int wm = wid & 3, wn = wid >> 2;
    int nbase = blockIdx.x * 128;

    // ---- A prologue: stage zH/zL rows into stage0, swizzled ----
    {
        const int4* h4 = (const int4*)g_zH;
        const int4* l4 = (const int4*)g_zL;
#pragma unroll
        for (int w = 0; w < 4; w++) {
            int i = tid + w * 256;
            int r = i >> 3, c = i & 7;
            cpa16(dbase + SW(r * 128 + c * 16), &h4[(nbase + r) * 8 + c]);
            cpa16(dbase + 16384 + SW(r * 128 + c * 16), &l4[(nbase + r) * 8 + c]);
        }
        CP_COMMIT();
        CP_WAIT0();
        __syncthreads();
    }

    // ---- load A fragments (held in registers for whole kernel) ----
    uint32_t ah[2][4][4], al[2][4][4];
    {
        int rA = ((lane >> 3) & 1) * 8 + (lane & 7);
        int kA = (lane >> 4) * 16;
#pragma unroll
        for (int mf = 0; mf < 2; mf++)
#pragma unroll
            for (int ks = 0; ks < 4; ks++) {
                uint32_t off = SW((uint32_t)((wm * 32 + mf * 16 + rA) * 128 + ks * 32 + kA));
                ldsm4(ah[mf][ks], dbase + off);
                ldsm4(al[mf][ks], dbase + 16384 + off);
            }
    }
    __syncthreads();   // done reading stage0 before B pipeline reuses it

    // ---- precompute swizzled B ldmatrix offsets (lane-dependent, stage-invariant) ----
    uint32_t offB[4][4];
    {
        int rB = ((lane >> 4) & 1) * 8 + (lane & 7);
        int kB = ((lane >> 3) & 1) * 16;
#pragma unroll
        for (int ks = 0; ks < 4; ks++)
#pragma unroll
            for (int p = 0; p < 4; p++)
                offB[ks][p] = SW((uint32_t)((wn * 64 + p * 16 + rB) * 128 + ks * 32 + kB));
    }

    // ---- prefetch offsets ----
    uint32_t pf_s[4];
    int pf_g[4];
#pragma unroll
    for (int w = 0; w < 4; w++) {
        int i = tid + w * 256;
        int r = i >> 3, c = i & 7;
        pf_s[w] = SW((uint32_t)(r * 128 + c * 16));
        pf_g[w] = r * 8 + c;
    }
    const int4* cbh4 = (const int4*)g_cbH;
    const int4* cbl4 = (const int4*)g_cbL;

    auto prefetch = [&](int nt) {
        uint32_t st = dbase + (nt & 3) * 32768;
#pragma unroll
        for (int w = 0; w < 4; w++) {
            cpa16(st + pf_s[w], &cbh4[nt * 1024 + pf_g[w]]);
            cpa16(st + 16384 + pf_s[w], &cbl4[nt * 1024 + pf_g[w]]);
        }
        CP_COMMIT();
    };

    prefetch(0); prefetch(1); prefetch(2);

    float g1[4], g2[4];
    int gi[4];
#pragma unroll
    for (int s = 0; s < 4; s++) { g1[s] = -1e30f; g2[s] = -1e30f; gi[s] = 0; }

    for (int nt = 0; nt < NTILES; nt++) {
        CP_WAIT2();
        __syncthreads();
        if (nt < NTILES - 3) prefetch(nt + 3);
        uint32_t stage = dbase + (nt & 3) * 32768;

        float C[2][8][4];
#pragma unroll
        for (int mf = 0; mf < 2; mf++)
#pragma unroll
            for (int j = 0; j < 8; j++)
#pragma unroll
                for (int q = 0; q < 4; q++) C[mf][j][q] = 0.0f;

#pragma unroll
        for (int ks = 0; ks < 4; ks++) {
            // issue ALL ldsm for this k-slice up front so LSU overlaps the MMA stream
            uint32_t bh[4][4], bl[4][4];
#pragma unroll
            for (int p = 0; p < 4; p++) ldsm4(bh[p], stage + offB[ks][p]);
#pragma unroll
            for (int p = 0; p < 4; p++) ldsm4(bl[p], stage + 16384 + offB[ks][p]);
#pragma unroll
            for (int mf = 0; mf < 2; mf++)
#pragma unroll
                for (int p = 0; p < 4; p++) {
                    mma_bf16(C[mf][2 * p],     ah[mf][ks], bh[p][0], bh[p][1]);
                    mma_bf16(C[mf][2 * p + 1], ah[mf][ks], bh[p][2], bh[p][3]);
                }
#pragma unroll
            for (int mf = 0; mf < 2; mf++)
#pragma unroll
                for (int p = 0; p < 4; p++) {
                    mma_bf16(C[mf][2 * p],     al[mf][ks], bh[p][0], bh[p][1]);
                    mma_bf16(C[mf][2 * p + 1], al[mf][ks], bh[p][2], bh[p][3]);
                }
#pragma unroll
            for (int mf = 0; mf < 2; mf++)
#pragma unroll
                for (int p = 0; p < 4; p++) {
                    mma_bf16(C[mf][2 * p],     ah[mf][ks], bl[p][0], bl[p][1]);
                    mma_bf16(C[mf][2 * p + 1], ah[mf][ks], bl[p][2], bl[p][3]);
                }
        }

        // ---- running top-2 argmax update ----
        int cb = nt * 128 + wn * 64 + (lane & 3) * 2;
#pragma unroll
        for (int mf = 0; mf < 2; mf++)
#pragma unroll
            for (int h = 0; h < 2; h++) {
                int s = mf * 2 + h;
                float m[8];
#pragma unroll
                for (int j = 0; j < 8; j++)
                    m[j] = fmaxf(C[mf][j][2 * h], C[mf][j][2 * h + 1]);
                m[0] = fmaxf(m[0], m[1]); m[2] = fmaxf(m[2], m[3]);
                m[4] = fmaxf(m[4], m[5]); m[6] = fmaxf(m[6], m[7]);
                m[0] = fmaxf(m[0], m[2]); m[4] = fmaxf(m[4], m[6]);
                float tm = fmaxf(m[0], m[4]);
                if (tm > g1[s]) {
                    float m1 = -1e30f, m2 = -1e30f;
                    int mi = 0;
#pragma unroll
                    for (int j = 0; j < 8; j++)
#pragma unroll
                        for (int c = 0; c < 2; c++) {
                            float v = C[mf][j][2 * h + c];
                            int col = cb + j * 8 + c;
                            if (v > m1) { m2 = m1; m1 = v; mi = col; }
                            else if (v > m2) { m2 = v; }
                        }
                    g2[s] = fmaxf(g1[s], m2);
                    g1[s] = m1;
                    gi[s] = mi;
                } else {
                    g2[s] = fmaxf(g2[s], tm);
                }
            }
    }
    __syncthreads();

    // ---- quad reduce (lanes sharing rows: lane^1, lane^2) ----
#pragma unroll
    for (int s = 0; s < 4; s++) {
#pragma unroll
        for (int d = 1; d <= 2; d <<= 1) {
            float ov1 = __shfl_xor_sync(0xFFFFFFFFu, g1[s], d);
            float ov2 = __shfl_xor_sync(0xFFFFFFFFu, g2[s], d);
            int   oi  = __shfl_xor_sync(0xFFFFFFFFu, gi[s], d);
            if (ov1 > g1[s]) { g2[s] = fmaxf(g1[s], ov2); g1[s] = ov1; gi[s] = oi; }
            else {
                if (ov1 == g1[s] && oi < gi[s]) gi[s] = oi;
                g2[s] = fmaxf(g2[s], ov1);
            }
        }
    }

    // ---- cross-warp (wn) reduce via smem ----
    float* rv1 = (float*)dp;          // [2][128]
    float* rv2 = rv1 + 256;           // [2][128]
    int*   ri  = (int*)(rv2 + 256);   // [2][128]
    if ((lane & 3) == 0) {
#pragma unroll
        for (int s = 0; s < 4; s++) {
            int mf = s >> 1, h = s & 1;
            int row = wm * 32 + mf * 16 + h * 8 + (lane >> 2);
            rv1[wn * 128 + row] = g1[s];
            rv2[wn * 128 + row] = g2[s];
            ri[wn * 128 + row]  = gi[s];
        }
    }
    __syncthreads();
    if (tid < 128) {
        float a1 = rv1[tid], a2 = rv2[tid];
        int   ai = ri[tid];
        float b1 = rv1[128 + tid], b2 = rv2[128 + tid];
        int   bi = ri[128 + tid];
        float v1, v2; int i1;
        if (b1 > a1)      { v1 = b1; v2 = fmaxf(a1, b2); i1 = bi; }
        else if (a1 > b1) { v1 = a1; v2 = fmaxf(a2, b1); i1 = ai; }
        else              { v1 = a1; v2 = a1; i1 = (ai < bi) ? ai : bi; }
        g_idx[nbase + tid] = i1;
        if (v1 - v2 < MARGIN) {
            int slot = atomicAdd(&g_nflag, 1);
            g_flag[slot] = nbase + tid;
        }
    }
}

// ---------------------------------------------------------------------------
// Exact fp32 rescore of flagged rows. warp per row.
__global__ void rescore_kernel(const float* __restrict__ z) {
    __shared__ float zrow[8][64];
    int wid = threadIdx.x >> 5, lane = threadIdx.x & 31;
    int gw = blockIdx.x * 8 + wid;
    int nf = g_nflag;
    for (int f = gw; f < nf; f += 64 * 8) {
        int n = g_flag[f];
        int b = n >> 10, hw = n & 1023;
        zrow[wid][lane]      = z[b * 65536 + lane * 1024 + hw];
        zrow[wid][lane + 32] = z[b * 65536 + (lane + 32) * 1024 + hw];
        __syncwarp();
        float v1 = -1e30f; int i1 = 0;
        for (int j = lane; j < K_CODES; j += 32) {
            const float4* cr = (const float4*)(g_cn + j * 64);
            float s = 0.0f;
#pragma unroll
            for (int q = 0; q < 16; q++) {
                float4 cv = cr[q];
                s += cv.x * zrow[wid][q * 4 + 0];
                s += cv.y * zrow[wid][q * 4 + 1];
                s += cv.z * zrow[wid][q * 4 + 2];
                s += cv.w * zrow[wid][q * 4 + 3];
            }
            if (s > v1) { v1 = s; i1 = j; }
        }
#pragma unroll
        for (int off = 16; off >= 1; off >>= 1) {
            float ov = __shfl_xor_sync(0xFFFFFFFFu, v1, off);
            int   oi = __shfl_xor_sync(0xFFFFFFFFu, i1, off);
            if (ov > v1 || (ov == v1 && oi < i1)) { v1 = ov; i1 = oi; }
        }
        if (lane == 0) g_idx[n] = i1;
        __syncwarp();
    }
}

// ---------------------------------------------------------------------------
__global__ void bincount_kernel() {
    int t = blockIdx.x * blockDim.x + threadIdx.x;
    if (t < N_VEC) atomicAdd(&g_bin[g_idx[t]], 1);
}

// ---------------------------------------------------------------------------
// Coalesced gather + loss.
__global__ void gather_kernel(const float* __restrict__ z,
                              const float* __restrict__ embed,
                              float* __restrict__ out) {
    __shared__ float qt[64 * 128];
    int t = threadIdx.x;
    int nbase = blockIdx.x * 128;
    int b = nbase >> 10, hw0 = nbase & 1023;

    {
        int r = t >> 1, half = t & 1;
        int idx = g_idx[nbase + r];
        const float4* er = (const float4*)(embed + idx * 64 + half * 32);
#pragma unroll
        for (int q = 0; q < 8; q++) {
            float4 v = er[q];
            int k = half * 32 + q * 4;
            qt[(k + 0) * 128 + r] = v.x;
            qt[(k + 1) * 128 + r] = v.y;
            qt[(k + 2) * 128 + r] = v.z;
            qt[(k + 3) * 128 + r] = v.w;
        }
    }
    __syncthreads();

    float s = 0.0f;
#pragma unroll
    for (int i = 0; i < 8; i++) {
        int f4 = t + i * 256;
        int k = f4 >> 5, hw4 = (f4 & 31) * 4;
        float4 qv = *(float4*)&qt[k * 128 + hw4];
        int off = b * 65536 + k * 1024 + hw0 + hw4;
        float4 zv = *(const float4*)&z[off];
        *(float4*)&out[off] = qv;
        float d0 = qv.x - zv.x, d1 = qv.y - zv.y, d2 = qv.z - zv.z, d3 = qv.w - zv.w;
        s += d0 * d0 + d1 * d1 + d2 * d2 + d3 * d3;
    }
#pragma unroll
    for (int off = 16; off >= 1; off >>= 1) s += __shfl_xor_sync(0xFFFFFFFFu, s, off);
    __shared__ float red[8];
    int lane = t & 31, wid = t >> 5;
    if (lane == 0) red[wid] = s;
    __syncthreads();
    if (wid == 0) {
        s = (lane < 8) ? red[lane] : 0.0f;
#pragma unroll
        for (int off = 4; off >= 1; off >>= 1) s += __shfl_xor_sync(0xFFFFFFFFu, s, off);
        if (lane == 0) atomicAdd(&g_lossd, (double)s);
    }
}

// ---------------------------------------------------------------------------
__global__ void finalize_kernel(float* __restrict__ out) {
    int t = blockIdx.x * blockDim.x + threadIdx.x;
    if (t == 0)
        out[OUT_ELEMS] = (float)(1.25 * g_lossd * (1.0 / (double)OUT_ELEMS));
    if (t < N_VEC)
        out[OUT_ELEMS + 1 + t] = (float)g_idx[t];
    if (t < K_CODES)
        out[OUT_ELEMS + 1 + N_VEC + t] = (float)g_bin[t];
}

// ---------------------------------------------------------------------------
extern "C" void kernel_launch(void* const* d_in, const int* in_sizes, int n_in,
                              void* d_out, int out_size) {
    const float* z     = (const float*)d_in[0];       // [16,64,32,32]
    const float* embed = (const float*)d_in[1];       // [8192,64]
    float* out = (float*)d_out;

    cudaFuncSetAttribute(hmma_argmax_kernel,
                         cudaFuncAttributeMaxDynamicSharedMemorySize, 132096);

    zero_kernel<<<64, 256>>>();
    norm_split_kernel<<<K_CODES / 8, 256>>>(embed);
    z_split_kernel<<<128, 256>>>(z);
    hmma_argmax_kernel<<<128, 256, 132096>>>();
    rescore_kernel<<<64, 256>>>(z);
    bincount_kernel<<<64, 256>>>();
    gather_kernel<<<128, 256>>>(z, embed, out);
    finalize_kernel<<<96, 256>>>(out);
}

// round 7
// speedup vs baseline: 1.2202x; 1.0018x over previous
#include <cuda_runtime.h>
#include <cuda_bf16.h>
#include <math.h>
#include <stdint.h>

#define N_VEC   16384
#define K_CODES 8192
#define DDIM    64
#define OUT_ELEMS 1048576            // 16*64*32*32
#define NTILES  64                   // 8192 / 128
#define MARGIN  1e-4f

// ---------------------------------------------------------------------------
// scratch (no cudaMalloc allowed)
__device__ __align__(256) float          g_cn[K_CODES * DDIM];   // normalized codebook fp32
__device__ __align__(256) __nv_bfloat16  g_cbH[K_CODES * DDIM];  // normalized codebook bf16 hi
__device__ __align__(256) __nv_bfloat16  g_cbL[K_CODES * DDIM];  // lo
__device__ __align__(256) __nv_bfloat16  g_zH[N_VEC * DDIM];     // z transposed [n][k] bf16 hi
__device__ __align__(256) __nv_bfloat16  g_zL[N_VEC * DDIM];     // lo
__device__ int    g_idx[N_VEC];
__device__ int    g_bin[K_CODES];
__device__ int    g_flag[N_VEC];
__device__ int    g_nflag;
__device__ double g_lossd;

// ---------------------------------------------------------------------------
__device__ __forceinline__ uint32_t smem_u32(const void* p) {
    uint32_t a;
    asm("{ .reg .u64 t; cvta.to.shared.u64 t, %1; cvt.u32.u64 %0, t; }"
        : "=r"(a) : "l"(p));
    return a;
}
__device__ __forceinline__ void cpa16(uint32_t s, const void* g) {
    asm volatile("cp.async.cg.shared.global [%0], [%1], 16;" :: "r"(s), "l"(g));
}
#define CP_COMMIT() asm volatile("cp.async.commit_group;" ::: "memory")
#define CP_WAIT0()  asm volatile("cp.async.wait_group 0;" ::: "memory")
#define CP_WAIT1()  asm volatile("cp.async.wait_group 1;" ::: "memory")

__device__ __forceinline__ void ldsm4(uint32_t* r, uint32_t addr) {
    asm volatile("ldmatrix.sync.aligned.m8n8.x4.shared.b16 {%0,%1,%2,%3}, [%4];"
                 : "=r"(r[0]), "=r"(r[1]), "=r"(r[2]), "=r"(r[3]) : "r"(addr));
}
__device__ __forceinline__ void mma_bf16(float* c, const uint32_t* a,
                                         uint32_t b0, uint32_t b1) {
    asm volatile("mma.sync.aligned.m16n8k16.row.col.f32.bf16.bf16.f32 "
                 "{%0,%1,%2,%3}, {%4,%5,%6,%7}, {%8,%9}, {%0,%1,%2,%3};"
                 : "+f"(c[0]), "+f"(c[1]), "+f"(c[2]), "+f"(c[3])
                 : "r"(a[0]), "r"(a[1]), "r"(a[2]), "r"(a[3]), "r"(b0), "r"(b1));
}
#define SW(x) ((x) ^ (((x) >> 3) & 0x70))

// ---------------------------------------------------------------------------
__global__ void zero_kernel() {
    int t = blockIdx.x * blockDim.x + threadIdx.x;
    if (t < K_CODES) g_bin[t] = 0;
    if (t == 0) { g_lossd = 0.0; g_nflag = 0; }
}

// ---------------------------------------------------------------------------
// Normalize codebook -> fp32 + bf16 hi/lo. warp per row.
__global__ void norm_split_kernel(const float* __restrict__ embed) {
    int wid = threadIdx.x >> 5, lane = threadIdx.x & 31;
    int row = blockIdx.x * 8 + wid;
    float a = embed[row * 64 + lane];
    float b = embed[row * 64 + lane + 32];
    float s = a * a + b * b;
#pragma unroll
    for (int off = 16; off >= 1; off >>= 1) s += __shfl_xor_sync(0xFFFFFFFFu, s, off);
    float inv = 1.0f / fmaxf(sqrtf(s), 1e-12f);
    float ca = a * inv, cb = b * inv;
    g_cn[row * 64 + lane] = ca;
    g_cn[row * 64 + lane + 32] = cb;
    __nv_bfloat16 ha = __float2bfloat16(ca), hb = __float2bfloat16(cb);
    g_cbH[row * 64 + lane] = ha;
    g_cbH[row * 64 + lane + 32] = hb;
    g_cbL[row * 64 + lane] = __float2bfloat16(ca - __bfloat162float(ha));
    g_cbL[row * 64 + lane + 32] = __float2bfloat16(cb - __bfloat162float(hb));
}

// ---------------------------------------------------------------------------
// Transpose z -> [n][k] bf16 hi/lo. Padded smem (stride 132) kills the 32-way
// bank conflicts; packed bf16x2 stores replace 2-byte scalar stores.
#define TSTR 132
__global__ void z_split_kernel(const float* __restrict__ z) {
    __shared__ float tile[64 * TSTR];
    int b = blockIdx.x >> 3;
    int hwb = blockIdx.x & 7;
    int t = threadIdx.x;
    const float4* z4 = (const float4*)z;
#pragma unroll
    for (int i = 0; i < 8; i++) {
        int f4 = t + i * 256;
        int k = f4 >> 5, w = f4 & 31;
        *(float4*)&tile[k * TSTR + w * 4] = z4[b * 16384 + k * 256 + hwb * 32 + w];
    }
    __syncthreads();
    int r = t >> 1, half = t & 1;
    int n = b * 1024 + hwb * 128 + r;
    __nv_bfloat162* zh2 = (__nv_bfloat162*)g_zH;
    __nv_bfloat162* zl2 = (__nv_bfloat162*)g_zL;
#pragma unroll
    for (int kk = 0; kk < 16; kk++) {
        int k = half * 32 + kk * 2;
        float v0 = tile[k * TSTR + r];
        float v1 = tile[(k + 1) * TSTR + r];
        __nv_bfloat162 hv = __floats2bfloat162_rn(v0, v1);
        __nv_bfloat162 lv = __floats2bfloat162_rn(v0 - __bfloat162float(hv.x),
                                                  v1 - __bfloat162float(hv.y));
        zh2[(n * 64 + k) >> 1] = hv;
        zl2[(n * 64 + k) >> 1] = lv;
    }
}

// ---------------------------------------------------------------------------
// Main kernel: mma.sync bf16x3 GEMM + fused running argmax (top-2).
// 256 CTAs x 128 threads, 2 CTAs/SM. Warp grid 2(M) x 2(N), 64 rows/CTA.
// Dyn smem: 3 stages x 32KB (Bh 16K | Bl 16K), 1024-aligned. A uses stage0
// transiently at startup (8K hi + 8K lo).
extern __shared__ char dsm[];
__global__ void __launch_bounds__(128, 2) hmma_argmax_kernel() {
    uint32_t sraw = smem_u32(dsm);
    uint32_t dbase = (sraw + 1023) & ~1023u;
    char* dp = dsm + (int)(dbase - sraw);
    int tid = threadIdx.x, lane = tid & 31, wid = tid >> 5;
    int wm = wid & 1, wn = wid >> 1;
    int nbase = blockIdx.x * 64;

    // ---- A prologue: stage zH/zL (64 rows) into stage0, swizzled ----
    {
        const int4* h4 = (const int4*)g_zH;
        const int4* l4 = (const int4*)g_zL;
#pragma unroll
        for (int w = 0; w < 4; w++) {
            int i = tid + w * 128;           // 512 chunks of 16B
            int r = i >> 3, c = i & 7;
            cpa16(dbase + SW(r * 128 + c * 16), &h4[(nbase + r) * 8 + c]);
            cpa16(dbase + 8192 + SW(r * 128 + c * 16), &l4[(nbase + r) * 8 + c]);
        }
        CP_COMMIT();
        CP_WAIT0();
        __syncthreads();
    }

    // ---- load A fragments (held in registers for whole kernel) ----
    uint32_t ah[2][4][4], al[2][4][4];
    {
        int rA = ((lane >> 3) & 1) * 8 + (lane & 7);
        int kA = (lane >> 4) * 16;
#pragma unroll
        for (int mf = 0; mf < 2; mf++)
#pragma unroll
            for (int ks = 0; ks < 4; ks++) {
                uint32_t off = SW((uint32_t)((wm * 32 + mf * 16 + rA) * 128 + ks * 32 + kA));
                ldsm4(ah[mf][ks], dbase + off);
                ldsm4(al[mf][ks], dbase + 8192 + off);
            }
    }
    __syncthreads();   // done reading stage0 before B pipeline reuses it

    // ---- precompute swizzled B ldmatrix offsets ----
    uint32_t offB[4][4];
    {
        int rB = ((lane >> 4) & 1) * 8 + (lane & 7);
        int kB = ((lane >> 3) & 1) * 16;
#pragma unroll
        for (int ks = 0; ks < 4; ks++)
#pragma unroll
            for (int p = 0; p < 4; p++)
                offB[ks][p] = SW((uint32_t)((wn * 64 + p * 16 + rB) * 128 + ks * 32 + kB));
    }

    // ---- prefetch offsets (8 chunk slots per thread per array) ----
    uint32_t pf_s[8];
    int pf_g[8];
#pragma unroll
    for (int w = 0; w < 8; w++) {
        int i = tid + w * 128;               // 1024 chunks
        int r = i >> 3, c = i & 7;
        pf_s[w] = SW((uint32_t)(r * 128 + c * 16));
        pf_g[w] = r * 8 + c;
    }
    const int4* cbh4 = (const int4*)g_cbH;
    const int4* cbl4 = (const int4*)g_cbL;

    auto prefetch = [&](int nt) {
        uint32_t st = dbase + (nt % 3) * 32768;
#pragma unroll
        for (int w = 0; w < 8; w++) {
            cpa16(st + pf_s[w], &cbh4[nt * 1024 + pf_g[w]]);
            cpa16(st + 16384 + pf_s[w], &cbl4[nt * 1024 + pf_g[w]]);
        }
        CP_COMMIT();
    };

    prefetch(0); prefetch(1);

    float g1[4], g2[4];
    int gi[4];
#pragma unroll
    for (int s = 0; s < 4; s++) { g1[s] = -1e30f; g2[s] = -1e30f; gi[s] = 0; }

    for (int nt = 0; nt < NTILES; nt++) {
        CP_WAIT1();
        __syncthreads();
        if (nt < NTILES - 2) prefetch(nt + 2);
        uint32_t stage = dbase + (nt % 3) * 32768;

        float C[2][8][4];
#pragma unroll
        for (int mf = 0; mf < 2; mf++)
#pragma unroll
            for (int j = 0; j < 8; j++)
#pragma unroll
                for (int q = 0; q < 4; q++) C[mf][j][q] = 0.0f;

#pragma unroll
        for (int ks = 0; ks < 4; ks++) {
            uint32_t bh[4][4], bl[4][4];
#pragma unroll
            for (int p = 0; p < 4; p++) ldsm4(bh[p], stage + offB[ks][p]);
#pragma unroll
            for (int p = 0; p < 4; p++) ldsm4(bl[p], stage + 16384 + offB[ks][p]);
#pragma unroll
            for (int mf = 0; mf < 2; mf++)
#pragma unroll
                for (int p = 0; p < 4; p++) {
                    mma_bf16(C[mf][2 * p],     ah[mf][ks], bh[p][0], bh[p][1]);
                    mma_bf16(C[mf][2 * p + 1], ah[mf][ks], bh[p][2], bh[p][3]);
                }
#pragma unroll
            for (int mf = 0; mf < 2; mf++)
#pragma unroll
                for (int p = 0; p < 4; p++) {
                    mma_bf16(C[mf][2 * p],     al[mf][ks], bh[p][0], bh[p][1]);
                    mma_bf16(C[mf][2 * p + 1], al[mf][ks], bh[p][2], bh[p][3]);
                }
#pragma unroll
            for (int mf = 0; mf < 2; mf++)
#pragma unroll
                for (int p = 0; p < 4; p++) {
                    mma_bf16(C[mf][2 * p],     ah[mf][ks], bl[p][0], bl[p][1]);
                    mma_bf16(C[mf][2 * p + 1], ah[mf][ks], bl[p][2], bl[p][3]);
                }
        }

        // ---- running top-2 argmax update ----
        int cb = nt * 128 + wn * 64 + (lane & 3) * 2;
#pragma unroll
        for (int mf = 0; mf < 2; mf++)
#pragma unroll
            for (int h = 0; h < 2; h++) {
                int s = mf * 2 + h;
                float m[8];
#pragma unroll
                for (int j = 0; j < 8; j++)
                    m[j] = fmaxf(C[mf][j][2 * h], C[mf][j][2 * h + 1]);
                m[0] = fmaxf(m[0], m[1]); m[2] = fmaxf(m[2], m[3]);
                m[4] = fmaxf(m[4], m[5]); m[6] = fmaxf(m[6], m[7]);
                m[0] = fmaxf(m[0], m[2]); m[4] = fmaxf(m[4], m[6]);
                float tm = fmaxf(m[0], m[4]);
                if (tm > g1[s]) {
                    float m1 = -1e30f, m2 = -1e30f;
                    int mi = 0;
#pragma unroll
                    for (int j = 0; j < 8; j++)
#pragma unroll
                        for (int c = 0; c < 2; c++) {
                            float v = C[mf][j][2 * h + c];
                            int col = cb + j * 8 + c;
                            if (v > m1) { m2 = m1; m1 = v; mi = col; }
                            else if (v > m2) { m2 = v; }
                        }
                    g2[s] = fmaxf(g1[s], m2);
                    g1[s] = m1;
                    gi[s] = mi;
                } else {
                    g2[s] = fmaxf(g2[s], tm);
                }
            }
    }
    __syncthreads();

    // ---- quad reduce (lanes sharing rows: lane^1, lane^2) ----
#pragma unroll
    for (int s = 0; s < 4; s++) {
#pragma unroll
        for (int d = 1; d <= 2; d <<= 1) {
            float ov1 = __shfl_xor_sync(0xFFFFFFFFu, g1[s], d);
            float ov2 = __shfl_xor_sync(0xFFFFFFFFu, g2[s], d);
            int   oi  = __shfl_xor_sync(0xFFFFFFFFu, gi[s], d);
            if (ov1 > g1[s]) { g2[s] = fmaxf(g1[s], ov2); g1[s] = ov1; gi[s] = oi; }
            else {
                if (ov1 == g1[s] && oi < gi[s]) gi[s] = oi;
                g2[s] = fmaxf(g2[s], ov1);
            }
        }
    }

    // ---- cross-warp (wn) reduce via smem ----
    float* rv1 = (float*)dp;          // [2][64]
    float* rv2 = rv1 + 128;
    int*   ri  = (int*)(rv2 + 128);
    if ((lane & 3) == 0) {
#pragma unroll
        for (int s = 0; s < 4; s++) {
            int mf = s >> 1, h = s & 1;
            int row = wm * 32 + mf * 16 + h * 8 + (lane >> 2);
            rv1[wn * 64 + row] = g1[s];
            rv2[wn * 64 + row] = g2[s];
            ri[wn * 64 + row]  = gi[s];
        }
    }
    __syncthreads();
    if (tid < 64) {
        float a1 = rv1[tid], a2 = rv2[tid];
        int   ai = ri[tid];
        float b1 = rv1[64 + tid], b2 = rv2[64 + tid];
        int   bi = ri[64 + tid];
        float v1, v2; int i1;
        if (b1 > a1)      { v1 = b1; v2 = fmaxf(a1, b2); i1 = bi; }
        else if (a1 > b1) { v1 = a1; v2 = fmaxf(a2, b1); i1 = ai; }
        else              { v1 = a1; v2 = a1; i1 = (ai < bi) ? ai : bi; }
        g_idx[nbase + tid] = i1;
        if (v1 - v2 < MARGIN) {
            int slot = atomicAdd(&g_nflag, 1);
            g_flag[slot] = nbase + tid;
        }
    }
}

// ---------------------------------------------------------------------------
// Exact fp32 rescore of flagged rows. warp per row.
__global__ void rescore_kernel(const float* __restrict__ z) {
    __shared__ float zrow[8][64];
    int wid = threadIdx.x >> 5, lane = threadIdx.x & 31;
    int gw = blockIdx.x * 8 + wid;
    int nf = g_nflag;
    for (int f = gw; f < nf; f += 64 * 8) {
        int n = g_flag[f];
        int b = n >> 10, hw = n & 1023;
        zrow[wid][lane]      = z[b * 65536 + lane * 1024 + hw];
        zrow[wid][lane + 32] = z[b * 65536 + (lane + 32) * 1024 + hw];
        __syncwarp();
        float v1 = -1e30f; int i1 = 0;
        for (int j = lane; j < K_CODES; j += 32) {
            const float4* cr = (const float4*)(g_cn + j * 64);
            float s = 0.0f;
#pragma unroll
            for (int q = 0; q < 16; q++) {
                float4 cv = cr[q];
                s += cv.x * zrow[wid][q * 4 + 0];
                s += cv.y * zrow[wid][q * 4 + 1];
                s += cv.z * zrow[wid][q * 4 + 2];
                s += cv.w * zrow[wid][q * 4 + 3];
            }
            if (s > v1) { v1 = s; i1 = j; }
        }
#pragma unroll
        for (int off = 16; off >= 1; off >>= 1) {
            float ov = __shfl_xor_sync(0xFFFFFFFFu, v1, off);
            int   oi = __shfl_xor_sync(0xFFFFFFFFu, i1, off);
            if (ov > v1 || (ov == v1 && oi < i1)) { v1 = ov; i1 = oi; }
        }
        if (lane == 0) g_idx[n] = i1;
        __syncwarp();
    }
}

// ---------------------------------------------------------------------------
__global__ void bincount_kernel() {
    int t = blockIdx.x * blockDim.x + threadIdx.x;
    if (t < N_VEC) atomicAdd(&g_bin[g_idx[t]], 1);
}

// ---------------------------------------------------------------------------
// Coalesced gather + loss. Padded qt stride kills bank conflicts.
__global__ void gather_kernel(const float* __restrict__ z,
                              const float* __restrict__ embed,
                              float* __restrict__ out) {
    __shared__ float qt[64 * TSTR];
    int t = threadIdx.x;
    int nbase = blockIdx.x * 128;
    int b = nbase >> 10, hw0 = nbase & 1023;

    {
        int r = t >> 1, half = t & 1;
        int idx = g_idx[nbase + r];
        const float4* er = (const float4*)(embed + idx * 64 + half * 32);
#pragma unroll
        for (int q = 0; q < 8; q++) {
            float4 v = er[q];
            int k = half * 32 + q * 4;
            qt[(k + 0) * TSTR + r] = v.x;
            qt[(k + 1) * TSTR + r] = v.y;
            qt[(k + 2) * TSTR + r] = v.z;
            qt[(k + 3) * TSTR + r] = v.w;
        }
    }
    __syncthreads();

    float s = 0.0f;
#pragma unroll
    for (int i = 0; i < 8; i++) {
        int f4 = t + i * 256;
        int k = f4 >> 5, hw4 = (f4 & 31) * 4;
        float4 qv = *(float4*)&qt[k * TSTR + hw4];
        int off = b * 65536 + k * 1024 + hw0 + hw4;
        float4 zv = *(const float4*)&z[off];
        *(float4*)&out[off] = qv;
        float d0 = qv.x - zv.x, d1 = qv.y - zv.y, d2 = qv.z - zv.z, d3 = qv.w - zv.w;
        s += d0 * d0 + d1 * d1 + d2 * d2 + d3 * d3;
    }
#pragma unroll
    for (int off = 16; off >= 1; off >>= 1) s += __shfl_xor_sync(0xFFFFFFFFu, s, off);
    __shared__ float red[8];
    int lane = t & 31, wid = t >> 5;
    if (lane == 0) red[wid] = s;
    __syncthreads();
    if (wid == 0) {
        s = (lane < 8) ? red[lane] : 0.0f;
#pragma unroll
        for (int off = 4; off >= 1; off >>= 1) s += __shfl_xor_sync(0xFFFFFFFFu, s, off);
        if (lane == 0) atomicAdd(&g_lossd, (double)s);
    }
}

// ---------------------------------------------------------------------------
__global__ void finalize_kernel(float* __restrict__ out) {
    int t = blockIdx.x * blockDim.x + threadIdx.x;
    if (t == 0)
        out[OUT_ELEMS] = (float)(1.25 * g_lossd * (1.0 / (double)OUT_ELEMS));
    if (t < N_VEC)
        out[OUT_ELEMS + 1 + t] = (float)g_idx[t];
    if (t < K_CODES)
        out[OUT_ELEMS + 1 + N_VEC + t] = (float)g_bin[t];
}

// ---------------------------------------------------------------------------
extern "C" void kernel_launch(void* const* d_in, const int* in_sizes, int n_in,
                              void* d_out, int out_size) {
    const float* z     = (const float*)d_in[0];       // [16,64,32,32]
    const float* embed = (const float*)d_in[1];       // [8192,64]
    float* out = (float*)d_out;

    cudaFuncSetAttribute(hmma_argmax_kernel,
                         cudaFuncAttributeMaxDynamicSharedMemorySize, 99328);

    zero_kernel<<<64, 256>>>();
    norm_split_kernel<<<K_CODES / 8, 256>>>(embed);
    z_split_kernel<<<128, 256>>>(z);
    hmma_argmax_kernel<<<256, 128, 99328>>>();
    rescore_kernel<<<64, 256>>>(z);
    bincount_kernel<<<64, 256>>>();
    gather_kernel<<<128, 256>>>(z, embed, out);
    finalize_kernel<<<96, 256>>>(out);
}